// round 3
// baseline (speedup 1.0000x reference)
#include <cuda_runtime.h>
#include <math.h>
#include <stdint.h>

#define Hh 256
#define Bb 512
#define Ss 168
#define Tt 24
#define Ff 16
#define G4 1024
#define SB (Ss*Bb)        // 86016
#define BH (Bb*Hh)        // 131072

// ---------------- static device scratch (no allocations allowed) ----------------
__device__ float g_pre[(size_t)SB * G4];   // 352 MB: input-projection gates, reused for both layers
__device__ float g_y0[(size_t)SB * Hh];    // 88 MB: layer-0 hidden sequence
__device__ float g_y1[(size_t)SB * Hh];    // 88 MB: layer-1 hidden sequence (= enc_out, [s][b][h])
__device__ float g_encp[(size_t)SB * Hh];  // 88 MB: enc_proj, [s][b][g]
__device__ float g_h0[2][BH];
__device__ float g_c0[2][BH];
__device__ float g_h1[2][BH];
__device__ float g_c1[2][BH];
__device__ float g_din[2][Bb];
__device__ float g_d[BH];                  // decoder attention query proj (B x H)
__device__ float g_scores[Bb * Ss];
__device__ float g_ctx[BH];

// ---------------- math helpers ----------------
__device__ __forceinline__ float sigf(float x) {
    return __fdividef(1.0f, 1.0f + __expf(-x));
}
__device__ __forceinline__ float tanh_ap(float x) {
    float y;
    asm("tanh.approx.f32 %0, %1;" : "=f"(y) : "f"(x));
    return y;
}

// ---------------- init: zero states, seed decoder input ----------------
__global__ void k_init(const float* __restrict__ src) {
    int i = blockIdx.x * blockDim.x + threadIdx.x;
    if (i < BH) {
        g_h0[0][i] = 0.f; g_c0[0][i] = 0.f;
        g_h1[0][i] = 0.f; g_c1[0][i] = 0.f;
    }
    if (i < Bb) {
        // dec_in0 = src[:, -1, -1]
        g_din[0][i] = src[(size_t)i * Ss * Ff + (Ss - 1) * Ff + (Ff - 1)];
    }
}

// ---------------- layer-0 input projection: pre[s][b][g] = b0[g] + src[b,s,:] @ Wih0[g,:] (K=16) ----------------
__global__ __launch_bounds__(256) void k_pre0(const float* __restrict__ src,
                                              const float* __restrict__ wih0,
                                              const float* __restrict__ b0) {
    int s   = blockIdx.z;
    int bb0 = blockIdx.y * 64;
    int g0  = blockIdx.x * 64;
    __shared__ float Xs[64][17];
    __shared__ float Ws[64][17];
    int tid = threadIdx.x;
    #pragma unroll
    for (int i = 0; i < 4; i++) {
        int idx = tid + i * 256;
        int r = idx >> 4, c = idx & 15;
        Xs[r][c] = src[(size_t)(bb0 + r) * (Ss * Ff) + s * Ff + c];
        Ws[r][c] = wih0[(g0 + r) * Ff + c];
    }
    __syncthreads();
    int tx = tid & 15, ty = tid >> 4;
    float acc[4][4] = {};
    #pragma unroll
    for (int k = 0; k < 16; k++) {
        float a[4], w[4];
        #pragma unroll
        for (int i = 0; i < 4; i++) a[i] = Xs[ty * 4 + i][k];
        #pragma unroll
        for (int j = 0; j < 4; j++) w[j] = Ws[tx * 4 + j][k];
        #pragma unroll
        for (int i = 0; i < 4; i++)
            #pragma unroll
            for (int j = 0; j < 4; j++) acc[i][j] += a[i] * w[j];
    }
    size_t base = (size_t)s * Bb * G4;
    #pragma unroll
    for (int i = 0; i < 4; i++) {
        int b = bb0 + ty * 4 + i;
        #pragma unroll
        for (int j = 0; j < 4; j++) {
            int g = g0 + tx * 4 + j;
            g_pre[base + (size_t)b * G4 + g] = acc[i][j] + b0[g];
        }
    }
}

// ---------------- generic GEMM: C[r][n] = (bias?bias[n]:0) + A[r,0:256] @ W[n,0:256], W row stride ldw ----------------
__global__ __launch_bounds__(256) void k_gemm256(const float* __restrict__ A,
                                                 const float* __restrict__ W, int ldw,
                                                 const float* __restrict__ bias,
                                                 float* __restrict__ C, int ldc) {
    int r0 = blockIdx.x * 64;
    int n0 = blockIdx.y * 64;
    __shared__ float As[64][33];
    __shared__ float Ws[64][33];
    int tid = threadIdx.x;
    int tx = tid & 15, ty = tid >> 4;
    float acc[4][4] = {};
    for (int k0 = 0; k0 < 256; k0 += 32) {
        #pragma unroll
        for (int i = 0; i < 8; i++) {
            int idx = tid + i * 256;
            int r = idx >> 5, c = idx & 31;
            As[r][c] = A[(size_t)(r0 + r) * 256 + k0 + c];
            Ws[r][c] = W[(size_t)(n0 + r) * ldw + k0 + c];
        }
        __syncthreads();
        #pragma unroll
        for (int k = 0; k < 32; k++) {
            float a[4], w[4];
            #pragma unroll
            for (int i = 0; i < 4; i++) a[i] = As[ty * 4 + i][k];
            #pragma unroll
            for (int j = 0; j < 4; j++) w[j] = Ws[tx * 4 + j][k];
            #pragma unroll
            for (int i = 0; i < 4; i++)
                #pragma unroll
                for (int j = 0; j < 4; j++) acc[i][j] += a[i] * w[j];
        }
        __syncthreads();
    }
    #pragma unroll
    for (int i = 0; i < 4; i++) {
        size_t r = r0 + ty * 4 + i;
        #pragma unroll
        for (int j = 0; j < 4; j++) {
            int n = n0 + tx * 4 + j;
            float bv = bias ? bias[n] : 0.f;
            C[r * ldc + n] = acc[i][j] + bv;
        }
    }
}

// ---------------- one encoder LSTM step: gates = pre[b,:] + h_prev @ Whh^T, fused activation ----------------
// CTA: 64 batches x 16 units (all 4 gate rows per unit live in the CTA).
__global__ __launch_bounds__(256) void k_lstm_step(const float* __restrict__ pre,
                                                   const float* __restrict__ hprev,
                                                   const float* __restrict__ cprev,
                                                   const float* __restrict__ whh,
                                                   float* __restrict__ hnext,
                                                   float* __restrict__ cnext,
                                                   float* __restrict__ yout) {
    int bb0 = blockIdx.x * 64;
    int ub  = blockIdx.y * 16;
    __shared__ float Hs[64][33];
    __shared__ float Ws[64][33];
    int tid = threadIdx.x, tx = tid & 15, ty = tid >> 4;
    float acc[4][4] = {};
    for (int k0 = 0; k0 < 256; k0 += 32) {
        #pragma unroll
        for (int i = 0; i < 8; i++) {
            int idx = tid + i * 256;
            int r = idx >> 5, c = idx & 31;
            Hs[r][c] = hprev[(bb0 + r) * 256 + k0 + c];
            int wr = (r & 3) * 256 + ub + (r >> 2);   // gate-interleaved weight rows
            Ws[r][c] = whh[wr * 256 + k0 + c];
        }
        __syncthreads();
        #pragma unroll
        for (int k = 0; k < 32; k++) {
            float a[4], w[4];
            #pragma unroll
            for (int i = 0; i < 4; i++) a[i] = Hs[ty * 4 + i][k];
            #pragma unroll
            for (int j = 0; j < 4; j++) w[j] = Ws[tx * 4 + j][k];
            #pragma unroll
            for (int i = 0; i < 4; i++)
                #pragma unroll
                for (int j = 0; j < 4; j++) acc[i][j] += a[i] * w[j];
        }
        __syncthreads();
    }
    int u = ub + tx;
    #pragma unroll
    for (int i = 0; i < 4; i++) {
        int b = bb0 + ty * 4 + i;
        const float* pb = pre + (size_t)b * G4;
        float gi = acc[i][0] + pb[u];
        float gf = acc[i][1] + pb[256 + u];
        float gg = acc[i][2] + pb[512 + u];
        float go = acc[i][3] + pb[768 + u];
        float c  = cprev[b * 256 + u];
        float cn = sigf(gf) * c + sigf(gi) * tanhf(gg);
        float hn = sigf(go) * tanhf(cn);
        hnext[b * 256 + u] = hn;
        cnext[b * 256 + u] = cn;
        if (yout) yout[b * 256 + u] = hn;
    }
}

// ---------------- decoder LSTM cell: gates = bias + [din]*wx[:,0] + xa @ wx[:,xoff:]^T + h @ whh^T ----------------
__global__ __launch_bounds__(256) void k_dec_cell(const float* __restrict__ xa,
                                                  const float* __restrict__ wx, int ldx, int xoff,
                                                  const float* __restrict__ din,
                                                  const float* __restrict__ hprev,
                                                  const float* __restrict__ cprev,
                                                  const float* __restrict__ whh,
                                                  const float* __restrict__ bias,
                                                  float* __restrict__ hnext,
                                                  float* __restrict__ cnext) {
    int bb0 = blockIdx.x * 64;
    int ub  = blockIdx.y * 16;
    __shared__ float As[64][33];
    __shared__ float Ws[64][33];
    int tid = threadIdx.x, tx = tid & 15, ty = tid >> 4;
    float acc[4][4] = {};
    // pass 1: xa @ wx^T   pass 2: hprev @ whh^T
    for (int pass = 0; pass < 2; pass++) {
        const float* Ain = pass ? hprev : xa;
        for (int k0 = 0; k0 < 256; k0 += 32) {
            #pragma unroll
            for (int i = 0; i < 8; i++) {
                int idx = tid + i * 256;
                int r = idx >> 5, c = idx & 31;
                As[r][c] = Ain[(bb0 + r) * 256 + k0 + c];
                int wr = (r & 3) * 256 + ub + (r >> 2);
                Ws[r][c] = pass ? whh[wr * 256 + k0 + c]
                                : wx[(size_t)wr * ldx + xoff + k0 + c];
            }
            __syncthreads();
            #pragma unroll
            for (int k = 0; k < 32; k++) {
                float a[4], w[4];
                #pragma unroll
                for (int i = 0; i < 4; i++) a[i] = As[ty * 4 + i][k];
                #pragma unroll
                for (int j = 0; j < 4; j++) w[j] = Ws[tx * 4 + j][k];
                #pragma unroll
                for (int i = 0; i < 4; i++)
                    #pragma unroll
                    for (int j = 0; j < 4; j++) acc[i][j] += a[i] * w[j];
            }
            __syncthreads();
        }
    }
    int u = ub + tx;
    float wcol0[4], bs[4];
    #pragma unroll
    for (int j = 0; j < 4; j++) {
        int row = j * 256 + u;
        bs[j] = bias[row];
        wcol0[j] = din ? wx[(size_t)row * ldx] : 0.f;
    }
    #pragma unroll
    for (int i = 0; i < 4; i++) {
        int b = bb0 + ty * 4 + i;
        float dv = din ? din[b] : 0.f;
        float gi = acc[i][0] + bs[0] + dv * wcol0[0];
        float gf = acc[i][1] + bs[1] + dv * wcol0[1];
        float gg = acc[i][2] + bs[2] + dv * wcol0[2];
        float go = acc[i][3] + bs[3] + dv * wcol0[3];
        float c  = cprev[b * 256 + u];
        float cn = sigf(gf) * c + sigf(gi) * tanhf(gg);
        float hn = sigf(go) * tanhf(cn);
        hnext[b * 256 + u] = hn;
        cnext[b * 256 + u] = cn;
    }
}

// ---------------- attention scores: scores[b,s] = sum_g tanh(encp[s,b,g] + d[b,g]) * v[g] ----------------
// (pos_bias * t/24 contracts to a per-b constant -> exactly cancelled by softmax; dropped)
__global__ void k_scores(const float* __restrict__ v) {
    int b = blockIdx.x;
    int wid = threadIdx.x >> 5, lane = threadIdx.x & 31;
    int s = blockIdx.y * 8 + wid;
    const float* ep = g_encp + ((size_t)s * Bb + b) * 256;
    const float* dd = g_d + b * 256;
    float acc = 0.f;
    #pragma unroll
    for (int i = 0; i < 8; i++) {
        int g = lane + i * 32;
        acc += tanh_ap(ep[g] + dd[g]) * v[g];
    }
    #pragma unroll
    for (int o = 16; o > 0; o >>= 1) acc += __shfl_xor_sync(0xffffffffu, acc, o);
    if (lane == 0) g_scores[b * Ss + s] = acc;
}

// ---------------- softmax over S + context: ctx[b,h] = sum_s w[b,s] * enc_out[s,b,h] ----------------
__global__ void k_softmax_ctx() {
    int b = blockIdx.x;
    int tid = threadIdx.x;
    __shared__ float wsm[Ss];
    __shared__ float red[256];
    float sv = (tid < Ss) ? g_scores[b * Ss + tid] : -1e30f;
    red[tid] = sv; __syncthreads();
    #pragma unroll
    for (int o = 128; o > 0; o >>= 1) { if (tid < o) red[tid] = fmaxf(red[tid], red[tid + o]); __syncthreads(); }
    float mx = red[0]; __syncthreads();
    float e = (tid < Ss) ? __expf(sv - mx) : 0.f;
    red[tid] = e; __syncthreads();
    #pragma unroll
    for (int o = 128; o > 0; o >>= 1) { if (tid < o) red[tid] += red[tid + o]; __syncthreads(); }
    float inv = __fdividef(1.f, red[0]);
    if (tid < Ss) wsm[tid] = e * inv;
    __syncthreads();
    float acc = 0.f;
    const float* Y = g_y1 + b * 256 + tid;
    #pragma unroll 4
    for (int s = 0; s < Ss; s++) acc += wsm[s] * Y[(size_t)s * Bb * 256];
    g_ctx[b * 256 + tid] = acc;
}

// ---------------- pred: out[b,t] = h1n[b,:] @ fc_w + fc_b ; feeds next dec_in ----------------
__global__ void k_pred(const float* __restrict__ h1n, const float* __restrict__ fcw,
                       const float* __restrict__ fcb, float* __restrict__ out,
                       float* __restrict__ din_next, int t) {
    int b = blockIdx.x;
    int tid = threadIdx.x;
    __shared__ float red[256];
    red[tid] = h1n[b * 256 + tid] * fcw[tid];
    __syncthreads();
    #pragma unroll
    for (int o = 128; o > 0; o >>= 1) { if (tid < o) red[tid] += red[tid + o]; __syncthreads(); }
    if (tid == 0) {
        float p = red[0] + fcb[0];
        out[b * Tt + t] = p;
        din_next[b] = p;
    }
}

// ---------------- host orchestration (graph-capturable: launches only) ----------------
extern "C" void kernel_launch(void* const* d_in, const int* in_sizes, int n_in,
                              void* d_out, int out_size) {
    const float* src   = (const float*)d_in[0];
    const float* ewih0 = (const float*)d_in[1];
    const float* ewhh0 = (const float*)d_in[2];
    const float* eb0   = (const float*)d_in[3];
    const float* ewih1 = (const float*)d_in[4];
    const float* ewhh1 = (const float*)d_in[5];
    const float* eb1   = (const float*)d_in[6];
    const float* dwih0 = (const float*)d_in[7];
    const float* dwhh0 = (const float*)d_in[8];
    const float* db0   = (const float*)d_in[9];
    const float* dwih1 = (const float*)d_in[10];
    const float* dwhh1 = (const float*)d_in[11];
    const float* db1   = (const float*)d_in[12];
    const float* attw  = (const float*)d_in[13];
    const float* attb  = (const float*)d_in[14];
    const float* attv  = (const float*)d_in[15];
    // d_in[16] = pos_bias: provably no effect (softmax shift invariance)
    const float* fcw   = (const float*)d_in[17];
    const float* fcb   = (const float*)d_in[18];
    float* out = (float*)d_out;

    float *pre, *y0, *y1, *encp, *h0, *c0, *h1, *c1, *din, *dvec, *ctx;
    cudaGetSymbolAddress((void**)&pre,  g_pre);
    cudaGetSymbolAddress((void**)&y0,   g_y0);
    cudaGetSymbolAddress((void**)&y1,   g_y1);
    cudaGetSymbolAddress((void**)&encp, g_encp);
    cudaGetSymbolAddress((void**)&h0,   g_h0);
    cudaGetSymbolAddress((void**)&c0,   g_c0);
    cudaGetSymbolAddress((void**)&h1,   g_h1);
    cudaGetSymbolAddress((void**)&c1,   g_c1);
    cudaGetSymbolAddress((void**)&din,  g_din);
    cudaGetSymbolAddress((void**)&dvec, g_d);
    cudaGetSymbolAddress((void**)&ctx,  g_ctx);

    k_init<<<(BH + 255) / 256, 256>>>(src);

    // encoder layer 0
    k_pre0<<<dim3(16, 8, Ss), 256>>>(src, ewih0, eb0);
    for (int t = 0; t < Ss; t++) {
        int cur = t & 1, nxt = (t + 1) & 1;
        k_lstm_step<<<dim3(8, 16), 256>>>(pre + (size_t)t * Bb * G4,
                                          h0 + cur * BH, c0 + cur * BH, ewhh0,
                                          h0 + nxt * BH, c0 + nxt * BH,
                                          y0 + (size_t)t * Bb * Hh);
    }

    // encoder layer 1: batched input projection then recurrence
    k_gemm256<<<dim3(SB / 64, 16), 256>>>(y0, ewih1, 256, eb1, pre, G4);
    for (int t = 0; t < Ss; t++) {
        int cur = t & 1, nxt = (t + 1) & 1;
        k_lstm_step<<<dim3(8, 16), 256>>>(pre + (size_t)t * Bb * G4,
                                          h1 + cur * BH, c1 + cur * BH, ewhh1,
                                          h1 + nxt * BH, c1 + nxt * BH,
                                          y1 + (size_t)t * Bb * Hh);
    }

    // enc_proj = enc_out @ We^T   (We = attn_w[:, :H], row stride 2H)
    k_gemm256<<<dim3(SB / 64, 4), 256>>>(y1, attw, 512, nullptr, encp, 256);

    // decoder
    for (int t = 0; t < Tt; t++) {
        int cur = t & 1, nxt = (t + 1) & 1;
        // d = h1 @ Wd^T + attn_b   (Wd = attn_w[:, H:], row stride 2H)
        k_gemm256<<<dim3(Bb / 64, 4), 256>>>(h1 + cur * BH, attw + 256, 512, attb, dvec, 256);
        k_scores<<<dim3(Bb, Ss / 8), 256>>>(attv);
        k_softmax_ctx<<<Bb, 256>>>();
        k_dec_cell<<<dim3(8, 16), 256>>>(ctx, dwih0, 1 + Hh, 1, din + cur * Bb,
                                         h0 + cur * BH, c0 + cur * BH, dwhh0, db0,
                                         h0 + nxt * BH, c0 + nxt * BH);
        k_dec_cell<<<dim3(8, 16), 256>>>(h0 + nxt * BH, dwih1, Hh, 0, nullptr,
                                         h1 + cur * BH, c1 + cur * BH, dwhh1, db1,
                                         h1 + nxt * BH, c1 + nxt * BH);
        k_pred<<<Bb, 256>>>(h1 + nxt * BH, fcw, fcb, out, din + nxt * Bb, t);
    }
}